// round 14
// baseline (speedup 1.0000x reference)
#include <cuda_runtime.h>
#include <cuda_bf16.h>
#include <cstdint>

// Problem constants (fixed by the reference setup_inputs)
#define B_  128
#define L_  2048
#define H_  768
#define H4_ 192          // H / 4 floats per float4
#define NSLICE 4
#define SLICE_W 48       // float4 columns per slice (48*16B = 768 B/row)
#define NTHREADS 192     // 48 cols x 4 row-groups

// Clamped inclusive span [start, end] for batch b, span s (0=head,1=tail).
// JAX x64 is disabled by default -> entity_positions arrives as int32.
__device__ __forceinline__ void span_bounds(const int* __restrict__ pos,
                                            int b, int s, int& start, int& end) {
    int p0 = pos[b * 4 + s * 2];
    int p1 = pos[b * 4 + s * 2 + 1];
    int st = p0 < 0 ? 0 : (p0 > (L_ - 1) ? (L_ - 1) : p0);
    int en = p1 > (L_ - 1) ? (L_ - 1) : p1;
    if (en < st) en = st;
    start = st;
    end   = en;
}

// One block per (H-slice, batch, span). Each block exclusively owns 48 float4
// output columns of one (b,s) and streams the ENTIRE span for that slice:
// no atomics, no zeroing, no scratch, every output element written exactly
// once. 192 threads = 48 columns x 4 row-groups; rows advance 4 at a time
// with a 4-deep unroll (16 rows / 4 independent loads in flight per thread).
__global__ void __launch_bounds__(NTHREADS)
entity_slice_kernel(const float4* __restrict__ seq4,
                    const int* __restrict__ pos,
                    float4* __restrict__ out4) {
    const int slice = blockIdx.x;   // 0..3
    const int b     = blockIdx.y;
    const int s     = blockIdx.z;

    int start, end;
    span_bounds(pos, b, s, start, end);
    const float inv = 1.0f / (float)(end - start + 1);

    const int t      = threadIdx.x;
    const int col    = t % SLICE_W;      // 0..47 (consecutive within warp-half)
    const int rowoff = t / SLICE_W;      // 0..3

    const float4* p = seq4 + (size_t)b * L_ * H4_ + slice * SLICE_W + col;

    float4 acc = make_float4(0.f, 0.f, 0.f, 0.f);

    int r = start + rowoff;
    // Main loop: 4 independent LDG.128 per thread (rows r, r+4, r+8, r+12).
    for (; r + 12 <= end; r += 16) {
        float4 v0 = __ldg(p + (size_t)(r +  0) * H4_);
        float4 v1 = __ldg(p + (size_t)(r +  4) * H4_);
        float4 v2 = __ldg(p + (size_t)(r +  8) * H4_);
        float4 v3 = __ldg(p + (size_t)(r + 12) * H4_);
        acc.x += (v0.x + v1.x) + (v2.x + v3.x);
        acc.y += (v0.y + v1.y) + (v2.y + v3.y);
        acc.z += (v0.z + v1.z) + (v2.z + v3.z);
        acc.w += (v0.w + v1.w) + (v2.w + v3.w);
    }
    for (; r <= end; r += 4) {
        float4 v = __ldg(p + (size_t)r * H4_);
        acc.x += v.x; acc.y += v.y; acc.z += v.z; acc.w += v.w;
    }

    // Cross-rowgroup reduction: 4 partials per column via shared memory.
    __shared__ float4 sred[NTHREADS];
    sred[t] = acc;
    __syncthreads();

    if (t < SLICE_W) {
        float4 a0 = sred[t];
        float4 a1 = sred[t + SLICE_W];
        float4 a2 = sred[t + 2 * SLICE_W];
        float4 a3 = sred[t + 3 * SLICE_W];
        float4 sum;
        sum.x = ((a0.x + a1.x) + (a2.x + a3.x)) * inv;
        sum.y = ((a0.y + a1.y) + (a2.y + a3.y)) * inv;
        sum.z = ((a0.z + a1.z) + (a2.z + a3.z)) * inv;
        sum.w = ((a0.w + a1.w) + (a2.w + a3.w)) * inv;
        out4[((size_t)s * B_ + b) * H4_ + slice * SLICE_W + t] = sum;
    }
}

extern "C" void kernel_launch(void* const* d_in, const int* in_sizes, int n_in,
                              void* d_out, int out_size) {
    const float4* seq4 = (const float4*)d_in[0];   // [B, L, H] fp32
    const int*    pos  = (const int*)d_in[1];      // [B, 4] int32
    float4* out4 = (float4*)d_out;                  // [2, B, H] fp32

    dim3 grid(NSLICE, B_, 2);                       // 1024 blocks, all wave-1
    entity_slice_kernel<<<grid, NTHREADS>>>(seq4, pos, out4);
}

// round 15
// speedup vs baseline: 1.9167x; 1.9167x over previous
#include <cuda_runtime.h>
#include <cuda_bf16.h>
#include <cstdint>

// Problem constants (fixed by the reference setup_inputs)
#define B_  128
#define L_  2048
#define H_  768
#define H4_ 192          // H / 4 floats per float4
#define CHUNK_ROWS 128
#define NCHUNKS (L_ / CHUNK_ROWS)   // 16
#define OUT_F4 ((2 * B_ * H_) / 4)  // 49152 float4 in the output

// Clamped inclusive span [start, end] for batch b, span s (0=head,1=tail).
// JAX x64 is disabled by default -> entity_positions arrives as int32.
__device__ __forceinline__ void span_bounds(const int* __restrict__ pos,
                                            int b, int s, int& start, int& end) {
    int p0 = pos[b * 4 + s * 2];
    int p1 = pos[b * 4 + s * 2 + 1];
    int st = p0 < 0 ? 0 : (p0 > (L_ - 1) ? (L_ - 1) : p0);
    int en = p1 > (L_ - 1) ? (L_ - 1) : p1;
    if (en < st) en = st;
    start = st;
    end   = en;
}

// Primary: zero the output accumulator. Fires programmatic launch completion
// at entry so the accum kernel starts streaming immediately; the zeroing
// itself (1.5 MB) finishes long before any worker reaches its atomics.
__global__ void entity_zero_kernel(float4* __restrict__ out4) {
    cudaTriggerProgrammaticLaunchCompletion();
    for (int i = blockIdx.x * blockDim.x + threadIdx.x; i < OUT_F4;
         i += gridDim.x * blockDim.x)
        out4[i] = make_float4(0.f, 0.f, 0.f, 0.f);
}

// Secondary: one block per (L-chunk, batch, span). 8-wide batched LDG.128
// loop, single accumulator (best measured streaming shape). Empty blocks
// exit WITHOUT the grid-dependency sync (they never touch d_out), freeing
// their SM slots instantly during ramp.
__global__ void __launch_bounds__(H4_)
entity_accum_kernel(const float4* __restrict__ seq4,
                    const int* __restrict__ pos,
                    float* __restrict__ out) {
    const int c = blockIdx.x;
    const int b = blockIdx.y;
    const int s = blockIdx.z;

    int start, end;
    span_bounds(pos, b, s, start, end);

    const int lo = max(start, c * CHUNK_ROWS);
    const int hi = min(end,   c * CHUNK_ROWS + CHUNK_ROWS - 1);
    if (lo > hi) return;   // no dependent-memory access -> no sync needed

    const float inv = 1.0f / (float)(end - start + 1);

    const int t = threadIdx.x;  // 0..191
    const float4* base = seq4 + (size_t)b * L_ * H4_ + t;

    float4 acc = make_float4(0.f, 0.f, 0.f, 0.f);

    int r = lo;
    // 8-row batched main loop: 8 independent LDG.128 in flight per thread.
    for (; r + 7 <= hi; r += 8) {
        float4 v0 = __ldg(base + (size_t)(r + 0) * H4_);
        float4 v1 = __ldg(base + (size_t)(r + 1) * H4_);
        float4 v2 = __ldg(base + (size_t)(r + 2) * H4_);
        float4 v3 = __ldg(base + (size_t)(r + 3) * H4_);
        float4 v4 = __ldg(base + (size_t)(r + 4) * H4_);
        float4 v5 = __ldg(base + (size_t)(r + 5) * H4_);
        float4 v6 = __ldg(base + (size_t)(r + 6) * H4_);
        float4 v7 = __ldg(base + (size_t)(r + 7) * H4_);
        acc.x += ((v0.x + v1.x) + (v2.x + v3.x)) + ((v4.x + v5.x) + (v6.x + v7.x));
        acc.y += ((v0.y + v1.y) + (v2.y + v3.y)) + ((v4.y + v5.y) + (v6.y + v7.y));
        acc.z += ((v0.z + v1.z) + (v2.z + v3.z)) + ((v4.z + v5.z) + (v6.z + v7.z));
        acc.w += ((v0.w + v1.w) + (v2.w + v3.w)) + ((v4.w + v5.w) + (v6.w + v7.w));
    }
    for (; r + 3 <= hi; r += 4) {
        float4 v0 = __ldg(base + (size_t)(r + 0) * H4_);
        float4 v1 = __ldg(base + (size_t)(r + 1) * H4_);
        float4 v2 = __ldg(base + (size_t)(r + 2) * H4_);
        float4 v3 = __ldg(base + (size_t)(r + 3) * H4_);
        acc.x += (v0.x + v1.x) + (v2.x + v3.x);
        acc.y += (v0.y + v1.y) + (v2.y + v3.y);
        acc.z += (v0.z + v1.z) + (v2.z + v3.z);
        acc.w += (v0.w + v1.w) + (v2.w + v3.w);
    }
    for (; r <= hi; ++r) {
        float4 v = __ldg(base + (size_t)r * H4_);
        acc.x += v.x; acc.y += v.y; acc.z += v.z; acc.w += v.w;
    }

    // Zero kernel is long finished by now; the wait is effectively free.
    cudaGridDependencySynchronize();

    float* o = out + ((size_t)s * B_ + b) * H_ + (size_t)t * 4;
    atomicAdd(o + 0, acc.x * inv);
    atomicAdd(o + 1, acc.y * inv);
    atomicAdd(o + 2, acc.z * inv);
    atomicAdd(o + 3, acc.w * inv);
}

extern "C" void kernel_launch(void* const* d_in, const int* in_sizes, int n_in,
                              void* d_out, int out_size) {
    const float4* seq4 = (const float4*)d_in[0];   // [B, L, H] fp32
    const int*    pos  = (const int*)d_in[1];      // [B, 4] int32
    float* out = (float*)d_out;                     // [2, B, H] fp32

    // Primary: zero kernel (PDL completion fired at entry).
    entity_zero_kernel<<<96, 512>>>((float4*)d_out);

    // Secondary: accum kernel overlapping the zero kernel via PDL.
    cudaLaunchConfig_t cfg = {};
    cfg.gridDim  = dim3(NCHUNKS, B_, 2);
    cfg.blockDim = dim3(H4_);
    cfg.dynamicSmemBytes = 0;
    cfg.stream = 0;
    cudaLaunchAttribute attrs[1];
    attrs[0].id = cudaLaunchAttributeProgrammaticStreamSerialization;
    attrs[0].val.programmaticStreamSerializationAllowed = 1;
    cfg.attrs = attrs;
    cfg.numAttrs = 1;
    cudaLaunchKernelEx(&cfg, entity_accum_kernel, seq4, pos, out);
}